// round 14
// baseline (speedup 1.0000x reference)
#include <cuda_runtime.h>
#include <cuda_bf16.h>
#include <cuda_fp16.h>

#define NN   20000
#define DD   8
#define KK   9
#define IN_F 64
#define HID  128
#define OUT  64
#define EE   100000
#define MTOT (NN * KK)
#define EPS  1e-5f
#define FULL 0xffffffffu

// ---------------- scratch ---------------------------------------------------
__device__ float  g_xW1[NN * HID];                 // x @ W1 (10.24 MB)
__device__ __half g_Qh[(size_t)MTOT * HID];        // prefix means, fp16 (46.08 MB) zero-init
__device__ int    g_cnt[MTOT];                     // query histogram (720 KB)
__device__ int    g_off[MTOT];                     // per-query row offset, -1 if masked (720 KB)
__device__ float  g_agg[NN * HID];                 // level-2 aggregated (10.24 MB)
__device__ float  g_z2[NN * OUT];                  // pre-BN layer-2 (5.12 MB)
__device__ __half g_emb[NN * OUT];                 // post-BN2 embeddings (2.56 MB)
__device__ float  g_s1[2 * HID];
__device__ float  g_s2[2 * OUT];
__device__ double g_loss;
__device__ unsigned g_done;

// ---------------- K1: init (fused) + xW1 = x @ W1 ---------------------------
__global__ void k_xw1(const float* __restrict__ x, const float* __restrict__ W1) {
    {
        int g = blockIdx.x * blockDim.x + threadIdx.x;
        for (int i = g; i < MTOT; i += gridDim.x * blockDim.x) g_cnt[i] = 0;
        if (blockIdx.x == 0) {
            int tt = threadIdx.x;
            if (tt < 2 * HID) g_s1[tt] = 0.f;
            if (tt < 2 * OUT) g_s2[tt] = 0.f;
            if (tt == 0) { g_loss = 0.0; g_done = 0u; }
        }
    }
    int t = threadIdx.x;            // column j in [0,128)
    float w[IN_F];
#pragma unroll
    for (int i = 0; i < IN_F; i++) w[i] = W1[i * HID + t];

    __shared__ __align__(16) float xs[4 * IN_F];
    for (int r0 = blockIdx.x * 4; r0 < NN; r0 += gridDim.x * 4) {
        __syncthreads();
        for (int i = t; i < 4 * IN_F; i += 128) xs[i] = x[r0 * IN_F + i];
        __syncthreads();
#pragma unroll
        for (int r = 0; r < 4; r++) {
            const float4* a4 = (const float4*)(xs + r * IN_F);
            float acc = 0.f;
#pragma unroll
            for (int ff = 0; ff < 16; ff++) {
                float4 a = a4[ff];
                acc = fmaf(a.x, w[4 * ff + 0], acc);
                acc = fmaf(a.y, w[4 * ff + 1], acc);
                acc = fmaf(a.z, w[4 * ff + 2], acc);
                acc = fmaf(a.w, w[4 * ff + 3], acc);
            }
            g_xW1[(r0 + r) * HID + t] = acc;
        }
    }
}

// ---------------- K2: query histogram + per-query offsets -------------------
__global__ void k_hist(const float* __restrict__ node_ts,
                       const int*   __restrict__ nidx,
                       const float* __restrict__ nts) {
    int m = blockIdx.x * blockDim.x + threadIdx.x;
    if (m >= MTOT) return;
    int n = m / 9, kc = m - n * 9;
    int ci; float cts; bool valid2;
    if (kc < DD) { ci = nidx[n * DD + kc]; cts = nts[n * DD + kc]; valid2 = (cts <= node_ts[n]); }
    else         { ci = n;                 cts = node_ts[n];       valid2 = true; }
    const float4* s4 = (const float4*)(nts + ci * 8);
    float4 a = s4[0], b = s4[1];
    int k = (a.x <= cts) + (a.y <= cts) + (a.z <= cts) + (a.w <= cts)
          + (b.x <= cts) + (b.y <= cts) + (b.z <= cts) + (b.w <= cts);
    int o = ci * KK + k;
    atomicAdd(&g_cnt[o], 1);
    g_off[m] = valid2 ? o : -1;
}

// ---------------- K3: warp-per-node prefix means + fused BN1 stats ----------
__global__ void k_build(const int* __restrict__ nidx, const float* __restrict__ nts) {
    int lane = threadIdx.x & 31, w = threadIdx.x >> 5;
    int wid = blockIdx.x * (blockDim.x >> 5) + w;
    int nw  = gridDim.x * (blockDim.x >> 5);

    float s0=0,s1=0,s2=0,s3=0, p0=0,p1=0,p2=0,p3=0;

    for (int c = wid; c < NN; c += nw) {
        float ts = 1e30f; int id = 0;
        if (lane < 8) { ts = nts[c * 8 + lane]; id = nidx[c * 8 + lane]; }
        int r = 0;
#pragma unroll
        for (int i = 0; i < 8; i++) {
            float o = __shfl_sync(FULL, ts, i);
            r += (o < ts) || (o == ts && i < lane);
        }
        int ids[8];
#pragma unroll
        for (int j = 0; j < 8; j++) {
            unsigned b = __ballot_sync(FULL, (lane < 8) && (r == j));
            int src = __ffs(b) - 1;
            ids[j] = __shfl_sync(FULL, id, src);
        }
        float wcl = (lane < 9) ? (float)g_cnt[c * KK + lane] : 0.f;
        float wj[9];
#pragma unroll
        for (int j = 0; j < 9; j++) wj[j] = __shfl_sync(FULL, wcl, j);

        float4 q = ((const float4*)(g_xW1 + (size_t)c * HID))[lane];
        float4 nb[8];
#pragma unroll
        for (int j = 0; j < 8; j++)
            nb[j] = ((const float4*)(g_xW1 + (size_t)ids[j] * HID))[lane];

        uint2* qb = (uint2*)(g_Qh + (size_t)c * KK * HID) + lane;  // row stride 32 uint2
        union { __half2 h[2]; uint2 u; } pk;

        if (wj[0] != 0.f) {
            pk.h[0] = __floats2half2_rn(q.x, q.y);
            pk.h[1] = __floats2half2_rn(q.z, q.w);
            qb[0] = pk.u;
            float w0 = wj[0];
            s0 += w0*q.x; p0 += w0*q.x*q.x;
            s1 += w0*q.y; p1 += w0*q.y*q.y;
            s2 += w0*q.z; p2 += w0*q.z*q.z;
            s3 += w0*q.w; p3 += w0*q.w*q.w;
        }
#pragma unroll
        for (int j = 0; j < 8; j++) {
            q.x += nb[j].x; q.y += nb[j].y; q.z += nb[j].z; q.w += nb[j].w;
            float wv = wj[j + 1];
            if (wv != 0.f) {
                float inv = 1.0f / (float)(j + 2);
                float mx = q.x*inv, my = q.y*inv, mz = q.z*inv, mw = q.w*inv;
                pk.h[0] = __floats2half2_rn(mx, my);
                pk.h[1] = __floats2half2_rn(mz, mw);
                qb[(j + 1) * 32] = pk.u;
                s0 += wv*mx; p0 += wv*mx*mx;
                s1 += wv*my; p1 += wv*my*my;
                s2 += wv*mz; p2 += wv*mz*mz;
                s3 += wv*mw; p3 += wv*mw*mw;
            }
        }
    }
    __shared__ float red[2 * HID];
    int t = threadIdx.x;
    if (t < 2 * HID) red[t] = 0.f;
    __syncthreads();
    atomicAdd(&red[4*lane + 0], s0); atomicAdd(&red[HID + 4*lane + 0], p0);
    atomicAdd(&red[4*lane + 1], s1); atomicAdd(&red[HID + 4*lane + 1], p1);
    atomicAdd(&red[4*lane + 2], s2); atomicAdd(&red[HID + 4*lane + 2], p2);
    atomicAdd(&red[4*lane + 3], s3); atomicAdd(&red[HID + 4*lane + 3], p3);
    __syncthreads();
    if (t < 2 * HID) atomicAdd(&g_s1[t], red[t]);
}

// ---------------- K4a: level-2 masked mean gather (warp per node, half2) ----
__global__ void k_agg(const float* __restrict__ g1, const float* __restrict__ be1) {
    int lane = threadIdx.x & 31, wa = threadIdx.x >> 5;
    int n = blockIdx.x * 8 + wa;
    if (n >= NN) return;

    __half2 sch0, sch1, shh0, shh1;
    {
        float inv = 1.0f / (float)MTOT;
        float4 s  = *(const float4*)(g_s1 + 4 * lane);
        float4 p  = *(const float4*)(g_s1 + HID + 4 * lane);
        float4 gg = *(const float4*)(g1 + 4 * lane);
        float4 bb = *(const float4*)(be1 + 4 * lane);
        float m0 = s.x*inv, m1 = s.y*inv, m2 = s.z*inv, m3 = s.w*inv;
        float c0 = gg.x * rsqrtf(p.x*inv - m0*m0 + EPS);
        float c1 = gg.y * rsqrtf(p.y*inv - m1*m1 + EPS);
        float c2 = gg.z * rsqrtf(p.z*inv - m2*m2 + EPS);
        float c3 = gg.w * rsqrtf(p.w*inv - m3*m3 + EPS);
        sch0 = __floats2half2_rn(c0, c1);
        sch1 = __floats2half2_rn(c2, c3);
        shh0 = __floats2half2_rn(bb.x - m0 * c0, bb.y - m1 * c1);
        shh1 = __floats2half2_rn(bb.z - m2 * c2, bb.w - m3 * c3);
    }

    int o2 = (lane < KK) ? g_off[n * KK + lane] : -1;
    float rc = 1.0f / (float)__popc(__ballot_sync(FULL, o2 >= 0));

    const __half2 one2  = __floats2half2_rn(1.f, 1.f);
    const __half2 zero2 = __floats2half2_rn(0.f, 0.f);

    int     oj[9];
    __half2 wt[9];
#pragma unroll
    for (int j = 0; j < 9; j++) {
        int v = __shfl_sync(FULL, o2, j);
        wt[j] = (v >= 0) ? one2 : zero2;
        oj[j] = (v >= 0) ? v : 0;
    }
    uint2 raw[9];
#pragma unroll
    for (int j = 0; j < 9; j++)
        raw[j] = *((const uint2*)(g_Qh + (size_t)oj[j] * HID) + lane);

    __half2 acc0 = zero2, acc1 = zero2;
#pragma unroll
    for (int j = 0; j < 9; j++) {
        union { uint2 u; __half2 h[2]; } pk; pk.u = raw[j];
        __half2 t0 = __hmax2(__hfma2(pk.h[0], sch0, shh0), zero2);
        __half2 t1 = __hmax2(__hfma2(pk.h[1], sch1, shh1), zero2);
        acc0 = __hfma2(wt[j], t0, acc0);
        acc1 = __hfma2(wt[j], t1, acc1);
    }
    float2 a0 = __half22float2(acc0);
    float2 a1 = __half22float2(acc1);
    float4 av = { a0.x * rc, a0.y * rc, a1.x * rc, a1.y * rc };
    *(float4*)(g_agg + (size_t)n * HID + 4 * lane) = av;
}

// ---------------- K4b: z2 = agg @ W2 + BN2 stats (8 nodes/iter) -------------
__global__ void k_gemm2(const float* __restrict__ W2) {
    int t = threadIdx.x;
    int o = t & 63, h = (t >> 6) & 1, gsel = t >> 7;
    float w[64];
#pragma unroll
    for (int i = 0; i < 64; i++) w[i] = W2[(h * 64 + i) * OUT + o];

    __shared__ __align__(16) float as[8][HID];
    __shared__ float bs[8][HID];

    float ssum = 0.f, ssq = 0.f;
    for (int n0 = blockIdx.x * 8; n0 < NN; n0 += gridDim.x * 8) {
        __syncthreads();
        ((float4*)as)[t] = ((const float4*)(g_agg + (size_t)n0 * HID))[t];
        __syncthreads();
#pragma unroll
        for (int gi = 0; gi < 4; gi++) {
            int g = gsel * 4 + gi;
            float a2 = 0.f;
            const float4* a4 = (const float4*)(as[g] + 64 * h);
#pragma unroll
            for (int ff = 0; ff < 16; ff++) {
                float4 v4 = a4[ff];
                a2 = fmaf(v4.x, w[4 * ff + 0], a2);
                a2 = fmaf(v4.y, w[4 * ff + 1], a2);
                a2 = fmaf(v4.z, w[4 * ff + 2], a2);
                a2 = fmaf(v4.w, w[4 * ff + 3], a2);
            }
            bs[g][o + 64 * h] = a2;
        }
        __syncthreads();
#pragma unroll
        for (int rep = 0; rep < 2; rep++) {
            int idx = t + 256 * rep;
            int g = idx >> 6, oo = idx & 63;
            float z2 = bs[g][oo] + bs[g][oo + 64];
            g_z2[(n0 + g) * OUT + oo] = z2;
            ssum += z2; ssq += z2 * z2;
        }
    }
    atomicAdd(&g_s2[t & 63], ssum);
    atomicAdd(&g_s2[OUT + (t & 63)], ssq);
}

// ---------------- K5: embeddings = relu(BN2(z2)) as fp16 (BN2 inline) -------
__global__ void k_embs(const float* __restrict__ g2, const float* __restrict__ be2) {
    int g = blockIdx.x * blockDim.x + threadIdx.x;   // one half2 (2 cols)
    if (g >= NN * 32) return;
    int n = g >> 5, cp = g & 31;
    int j0 = 2 * cp, j1 = 2 * cp + 1;
    float inv = 1.0f / (float)NN;
    float m0 = g_s2[j0] * inv, m1 = g_s2[j1] * inv;
    float v0 = g_s2[OUT + j0] * inv - m0 * m0;
    float v1 = g_s2[OUT + j1] * inv - m1 * m1;
    float sc0 = g2[j0] * rsqrtf(v0 + EPS);
    float sc1 = g2[j1] * rsqrtf(v1 + EPS);
    float sh0 = be2[j0] - m0 * sc0;
    float sh1 = be2[j1] - m1 * sc1;
    float2 z = *(const float2*)(g_z2 + n * OUT + j0);
    float ex = fmaxf(fmaf(z.x, sc0, sh0), 0.f);
    float ey = fmaxf(fmaf(z.y, sc1, sh1), 0.f);
    ((__half2*)g_emb)[g] = __floats2half2_rn(ex, ey);
}

// ---------------- K6: decoder + BCE; half-warp per pair, 8 pairs/warp-iter --
// Also finalizes the loss (done-counter) — no separate k_fin launch.
__global__ void k_dec(const int* __restrict__ target, const int* __restrict__ negp,
                      const float* __restrict__ Wd, const float* __restrict__ bd,
                      float* __restrict__ out) {
    int t = threadIdx.x, lane = t & 31, w = t >> 5;
    int lane16 = lane & 15, half = lane >> 4;
    int gw = blockIdx.x * 8 + w;
    int nw = gridDim.x * 8;

    float4 wd4 = *(const float4*)(Wd + 4 * lane16);
    float bdv = bd[0];

    float acc = 0.f;
    for (int base = gw * 8; base < 2 * EE; base += nw * 8) {
        // EE % 8 == 0 and base % 8 == 0 => chunk is purely pos or purely neg
        float y; const int* src; int off0;
        if (base < EE) { src = target; off0 = base;      y = 1.f; }
        else           { src = negp;   off0 = base - EE; y = 0.f; }
        const uint2* eb = (const uint2*)g_emb;   // row = 16 uint2 (4 halves each)
#pragma unroll
        for (int j = 0; j < 4; j++) {
            int p = off0 + 2 * j + half;
            int u = src[p], v = src[EE + p];
            uint2 ru = eb[u * 16 + lane16];
            uint2 rv = eb[v * 16 + lane16];
            union { uint2 u2; __half2 h[2]; } cu, cv;
            cu.u2 = ru; cv.u2 = rv;
            float2 u0 = __half22float2(cu.h[0]), u1 = __half22float2(cu.h[1]);
            float2 v0 = __half22float2(cv.h[0]), v1 = __half22float2(cv.h[1]);
            float d = u0.x * v0.x * wd4.x + u0.y * v0.y * wd4.y
                    + u1.x * v1.x * wd4.z + u1.y * v1.y * wd4.w;
#pragma unroll
            for (int s = 8; s > 0; s >>= 1) d += __shfl_xor_sync(FULL, d, s);
            if (lane16 == 0) {
                float pr = d + bdv;
                acc += fmaxf(pr, 0.f) - pr * y + log1pf(__expf(-fabsf(pr)));
            }
        }
    }
    // warp total: acc lives on lanes 0 and 16
    acc += __shfl_xor_sync(FULL, acc, 16);
    __shared__ float ws[8];
    if (lane == 0) ws[w] = acc;
    __syncthreads();
    if (t == 0) {
        float s = 0.f;
#pragma unroll
        for (int i = 0; i < 8; i++) s += ws[i];
        atomicAdd(&g_loss, (double)s);
        __threadfence();
        unsigned ticket = atomicAdd(&g_done, 1u);
        if (ticket == gridDim.x - 1)
            out[0] = (float)(g_loss * (1.0 / (double)(2 * EE)));
    }
}

// ---------------- launch ------------------------------------------------------
extern "C" void kernel_launch(void* const* d_in, const int* in_sizes, int n_in,
                              void* d_out, int out_size) {
    const float* x        = (const float*)d_in[0];
    const float* node_ts  = (const float*)d_in[1];
    const int*   nidx     = (const int*)  d_in[2];
    const float* nts      = (const float*)d_in[3];
    const int*   target   = (const int*)  d_in[4];
    const int*   negp     = (const int*)  d_in[5];
    const float* W1       = (const float*)d_in[6];
    const float* g1       = (const float*)d_in[8];
    const float* be1      = (const float*)d_in[9];
    const float* W2       = (const float*)d_in[10];
    const float* g2       = (const float*)d_in[12];
    const float* be2      = (const float*)d_in[13];
    const float* Wd       = (const float*)d_in[14];
    const float* bd       = (const float*)d_in[15];
    float* out = (float*)d_out;

    k_xw1   <<<1024, 128>>>(x, W1);
    k_hist  <<<(MTOT + 255) / 256, 256>>>(node_ts, nidx, nts);
    k_build <<<2500, 256>>>(nidx, nts);
    k_agg   <<<2500, 256>>>(g1, be1);
    k_gemm2 <<<1250, 256>>>(W2);
    k_embs  <<<(NN * 32 + 255) / 256, 256>>>(g2, be2);
    k_dec   <<<1600, 256>>>(target, negp, Wd, bd, out);
}

// round 15
// speedup vs baseline: 1.0823x; 1.0823x over previous
#include <cuda_runtime.h>
#include <cuda_bf16.h>
#include <cuda_fp16.h>

#define NN   20000
#define DD   8
#define KK   9
#define IN_F 64
#define HID  128
#define OUT  64
#define EE   100000
#define MTOT (NN * KK)
#define EPS  1e-5f
#define FULL 0xffffffffu

// ---------------- scratch ---------------------------------------------------
// Invariant: g_cnt, g_s1, g_s2, g_loss, g_done are ZERO at kernel_launch entry.
// (static zero-init covers the first execution; k_dec re-zeroes them at the
//  end of every execution, so each replay starts clean — deterministic.)
__device__ float  g_xW1[NN * HID];                 // x @ W1 (10.24 MB)
__device__ __half g_Qh[(size_t)MTOT * HID];        // prefix means, fp16 (46.08 MB)
__device__ int    g_cnt[MTOT];                     // query histogram (720 KB)
__device__ int    g_off[MTOT];                     // per-query row offset, -1 if masked
__device__ float  g_agg[NN * HID];                 // level-2 aggregated (10.24 MB)
__device__ float  g_z2[NN * OUT];                  // pre-BN layer-2 (5.12 MB)
__device__ float  g_s1[2 * HID];
__device__ float  g_s2[2 * OUT];
__device__ double g_loss;
__device__ unsigned g_done;

// ---------------- K1: xW1 = x @ W1  +  fused query histogram ---------------
__global__ void k_xw1(const float* __restrict__ x, const float* __restrict__ W1,
                      const float* __restrict__ node_ts,
                      const int*   __restrict__ nidx,
                      const float* __restrict__ nts) {
    // fused hist: g_cnt is pre-zeroed (invariant), so atomics are safe here
    {
        int g = blockIdx.x * blockDim.x + threadIdx.x;
        for (int m = g; m < MTOT; m += gridDim.x * blockDim.x) {
            int n = m / 9, kc = m - n * 9;
            int ci; float cts; bool valid2;
            if (kc < DD) { ci = nidx[n * DD + kc]; cts = nts[n * DD + kc]; valid2 = (cts <= node_ts[n]); }
            else         { ci = n;                 cts = node_ts[n];       valid2 = true; }
            const float4* s4 = (const float4*)(nts + ci * 8);
            float4 a = s4[0], b = s4[1];
            int k = (a.x <= cts) + (a.y <= cts) + (a.z <= cts) + (a.w <= cts)
                  + (b.x <= cts) + (b.y <= cts) + (b.z <= cts) + (b.w <= cts);
            int o = ci * KK + k;
            atomicAdd(&g_cnt[o], 1);
            g_off[m] = valid2 ? o : -1;
        }
    }
    int t = threadIdx.x;            // column j in [0,128)
    float w[IN_F];
#pragma unroll
    for (int i = 0; i < IN_F; i++) w[i] = W1[i * HID + t];

    __shared__ __align__(16) float xs[4 * IN_F];
    for (int r0 = blockIdx.x * 4; r0 < NN; r0 += gridDim.x * 4) {
        __syncthreads();
        for (int i = t; i < 4 * IN_F; i += 128) xs[i] = x[r0 * IN_F + i];
        __syncthreads();
#pragma unroll
        for (int r = 0; r < 4; r++) {
            const float4* a4 = (const float4*)(xs + r * IN_F);
            float acc = 0.f;
#pragma unroll
            for (int ff = 0; ff < 16; ff++) {
                float4 a = a4[ff];
                acc = fmaf(a.x, w[4 * ff + 0], acc);
                acc = fmaf(a.y, w[4 * ff + 1], acc);
                acc = fmaf(a.z, w[4 * ff + 2], acc);
                acc = fmaf(a.w, w[4 * ff + 3], acc);
            }
            g_xW1[(r0 + r) * HID + t] = acc;
        }
    }
}

// ---------------- K2: warp-per-node prefix means + fused BN1 stats ----------
__global__ void k_build(const int* __restrict__ nidx, const float* __restrict__ nts) {
    int lane = threadIdx.x & 31, w = threadIdx.x >> 5;
    int wid = blockIdx.x * (blockDim.x >> 5) + w;
    int nw  = gridDim.x * (blockDim.x >> 5);

    float s0=0,s1=0,s2=0,s3=0, p0=0,p1=0,p2=0,p3=0;

    for (int c = wid; c < NN; c += nw) {
        float ts = 1e30f; int id = 0;
        if (lane < 8) { ts = nts[c * 8 + lane]; id = nidx[c * 8 + lane]; }
        int r = 0;
#pragma unroll
        for (int i = 0; i < 8; i++) {
            float o = __shfl_sync(FULL, ts, i);
            r += (o < ts) || (o == ts && i < lane);
        }
        int ids[8];
#pragma unroll
        for (int j = 0; j < 8; j++) {
            unsigned b = __ballot_sync(FULL, (lane < 8) && (r == j));
            int src = __ffs(b) - 1;
            ids[j] = __shfl_sync(FULL, id, src);
        }
        float wcl = (lane < 9) ? (float)g_cnt[c * KK + lane] : 0.f;
        float wj[9];
#pragma unroll
        for (int j = 0; j < 9; j++) wj[j] = __shfl_sync(FULL, wcl, j);

        float4 q = ((const float4*)(g_xW1 + (size_t)c * HID))[lane];
        float4 nb[8];
#pragma unroll
        for (int j = 0; j < 8; j++)
            nb[j] = ((const float4*)(g_xW1 + (size_t)ids[j] * HID))[lane];

        uint2* qb = (uint2*)(g_Qh + (size_t)c * KK * HID) + lane;  // row stride 32 uint2
        union { __half2 h[2]; uint2 u; } pk;

        if (wj[0] != 0.f) {
            pk.h[0] = __floats2half2_rn(q.x, q.y);
            pk.h[1] = __floats2half2_rn(q.z, q.w);
            qb[0] = pk.u;
            float w0 = wj[0];
            s0 += w0*q.x; p0 += w0*q.x*q.x;
            s1 += w0*q.y; p1 += w0*q.y*q.y;
            s2 += w0*q.z; p2 += w0*q.z*q.z;
            s3 += w0*q.w; p3 += w0*q.w*q.w;
        }
#pragma unroll
        for (int j = 0; j < 8; j++) {
            q.x += nb[j].x; q.y += nb[j].y; q.z += nb[j].z; q.w += nb[j].w;
            float wv = wj[j + 1];
            if (wv != 0.f) {
                float inv = 1.0f / (float)(j + 2);
                float mx = q.x*inv, my = q.y*inv, mz = q.z*inv, mw = q.w*inv;
                pk.h[0] = __floats2half2_rn(mx, my);
                pk.h[1] = __floats2half2_rn(mz, mw);
                qb[(j + 1) * 32] = pk.u;
                s0 += wv*mx; p0 += wv*mx*mx;
                s1 += wv*my; p1 += wv*my*my;
                s2 += wv*mz; p2 += wv*mz*mz;
                s3 += wv*mw; p3 += wv*mw*mw;
            }
        }
    }
    __shared__ float red[2 * HID];
    int t = threadIdx.x;
    if (t < 2 * HID) red[t] = 0.f;
    __syncthreads();
    atomicAdd(&red[4*lane + 0], s0); atomicAdd(&red[HID + 4*lane + 0], p0);
    atomicAdd(&red[4*lane + 1], s1); atomicAdd(&red[HID + 4*lane + 1], p1);
    atomicAdd(&red[4*lane + 2], s2); atomicAdd(&red[HID + 4*lane + 2], p2);
    atomicAdd(&red[4*lane + 3], s3); atomicAdd(&red[HID + 4*lane + 3], p3);
    __syncthreads();
    if (t < 2 * HID) atomicAdd(&g_s1[t], red[t]);
}

// ---------------- K3: level-2 masked mean gather (warp per node, half2) -----
__global__ void k_agg(const float* __restrict__ g1, const float* __restrict__ be1) {
    int lane = threadIdx.x & 31, wa = threadIdx.x >> 5;
    int n = blockIdx.x * 8 + wa;
    if (n >= NN) return;

    __half2 sch0, sch1, shh0, shh1;
    {
        float inv = 1.0f / (float)MTOT;
        float4 s  = *(const float4*)(g_s1 + 4 * lane);
        float4 p  = *(const float4*)(g_s1 + HID + 4 * lane);
        float4 gg = *(const float4*)(g1 + 4 * lane);
        float4 bb = *(const float4*)(be1 + 4 * lane);
        float m0 = s.x*inv, m1 = s.y*inv, m2 = s.z*inv, m3 = s.w*inv;
        float c0 = gg.x * rsqrtf(p.x*inv - m0*m0 + EPS);
        float c1 = gg.y * rsqrtf(p.y*inv - m1*m1 + EPS);
        float c2 = gg.z * rsqrtf(p.z*inv - m2*m2 + EPS);
        float c3 = gg.w * rsqrtf(p.w*inv - m3*m3 + EPS);
        sch0 = __floats2half2_rn(c0, c1);
        sch1 = __floats2half2_rn(c2, c3);
        shh0 = __floats2half2_rn(bb.x - m0 * c0, bb.y - m1 * c1);
        shh1 = __floats2half2_rn(bb.z - m2 * c2, bb.w - m3 * c3);
    }

    int o2 = (lane < KK) ? g_off[n * KK + lane] : -1;
    float rc = 1.0f / (float)__popc(__ballot_sync(FULL, o2 >= 0));

    const __half2 one2  = __floats2half2_rn(1.f, 1.f);
    const __half2 zero2 = __floats2half2_rn(0.f, 0.f);

    int     oj[9];
    __half2 wt[9];
#pragma unroll
    for (int j = 0; j < 9; j++) {
        int v = __shfl_sync(FULL, o2, j);
        wt[j] = (v >= 0) ? one2 : zero2;
        oj[j] = (v >= 0) ? v : 0;
    }
    uint2 raw[9];
#pragma unroll
    for (int j = 0; j < 9; j++)
        raw[j] = *((const uint2*)(g_Qh + (size_t)oj[j] * HID) + lane);

    __half2 acc0 = zero2, acc1 = zero2;
#pragma unroll
    for (int j = 0; j < 9; j++) {
        union { uint2 u; __half2 h[2]; } pk; pk.u = raw[j];
        __half2 t0 = __hmax2(__hfma2(pk.h[0], sch0, shh0), zero2);
        __half2 t1 = __hmax2(__hfma2(pk.h[1], sch1, shh1), zero2);
        acc0 = __hfma2(wt[j], t0, acc0);
        acc1 = __hfma2(wt[j], t1, acc1);
    }
    float2 a0 = __half22float2(acc0);
    float2 a1 = __half22float2(acc1);
    float4 av = { a0.x * rc, a0.y * rc, a1.x * rc, a1.y * rc };
    *(float4*)(g_agg + (size_t)n * HID + 4 * lane) = av;
}

// ---------------- K4: z2 = agg @ W2 + BN2 stats (8 nodes/iter) --------------
__global__ void k_gemm2(const float* __restrict__ W2) {
    int t = threadIdx.x;
    int o = t & 63, h = (t >> 6) & 1, gsel = t >> 7;
    float w[64];
#pragma unroll
    for (int i = 0; i < 64; i++) w[i] = W2[(h * 64 + i) * OUT + o];

    __shared__ __align__(16) float as[8][HID];
    __shared__ float bs[8][HID];

    float ssum = 0.f, ssq = 0.f;
    for (int n0 = blockIdx.x * 8; n0 < NN; n0 += gridDim.x * 8) {
        __syncthreads();
        ((float4*)as)[t] = ((const float4*)(g_agg + (size_t)n0 * HID))[t];
        __syncthreads();
#pragma unroll
        for (int gi = 0; gi < 4; gi++) {
            int g = gsel * 4 + gi;
            float a2 = 0.f;
            const float4* a4 = (const float4*)(as[g] + 64 * h);
#pragma unroll
            for (int ff = 0; ff < 16; ff++) {
                float4 v4 = a4[ff];
                a2 = fmaf(v4.x, w[4 * ff + 0], a2);
                a2 = fmaf(v4.y, w[4 * ff + 1], a2);
                a2 = fmaf(v4.z, w[4 * ff + 2], a2);
                a2 = fmaf(v4.w, w[4 * ff + 3], a2);
            }
            bs[g][o + 64 * h] = a2;
        }
        __syncthreads();
#pragma unroll
        for (int rep = 0; rep < 2; rep++) {
            int idx = t + 256 * rep;
            int g = idx >> 6, oo = idx & 63;
            float z2 = bs[g][oo] + bs[g][oo + 64];
            g_z2[(n0 + g) * OUT + oo] = z2;
            ssum += z2; ssq += z2 * z2;
        }
    }
    atomicAdd(&g_s2[t & 63], ssum);
    atomicAdd(&g_s2[OUT + (t & 63)], ssq);
}

// ---------------- K5: decoder + BCE with inline BN2+ReLU, final + cleanup ---
// Half-warp per pair, 8 pairs/warp-iter. Reads z2 (fp32, L2-resident) and
// applies BN2 inline (no emb table). Last-ticket block writes the output and
// resets g_s2/g_loss/g_done; all blocks reset g_cnt/g_s1 for the next replay.
__global__ void k_dec(const int* __restrict__ target, const int* __restrict__ negp,
                      const float* __restrict__ Wd, const float* __restrict__ bd,
                      const float* __restrict__ g2, const float* __restrict__ be2,
                      float* __restrict__ out) {
    int t = threadIdx.x, lane = t & 31, w = t >> 5;
    int lane16 = lane & 15, half = lane >> 4;
    int gw = blockIdx.x * 8 + w;
    int nw = gridDim.x * 8;

    // BN2 params for cols 4*lane16 .. 4*lane16+3
    float4 sc4, sh4;
    {
        float inv = 1.0f / (float)NN;
        float4 s  = *(const float4*)(g_s2 + 4 * lane16);
        float4 p  = *(const float4*)(g_s2 + OUT + 4 * lane16);
        float4 gg = *(const float4*)(g2 + 4 * lane16);
        float4 bb = *(const float4*)(be2 + 4 * lane16);
        float m0 = s.x*inv, m1 = s.y*inv, m2 = s.z*inv, m3 = s.w*inv;
        sc4.x = gg.x * rsqrtf(p.x*inv - m0*m0 + EPS);
        sc4.y = gg.y * rsqrtf(p.y*inv - m1*m1 + EPS);
        sc4.z = gg.z * rsqrtf(p.z*inv - m2*m2 + EPS);
        sc4.w = gg.w * rsqrtf(p.w*inv - m3*m3 + EPS);
        sh4.x = bb.x - m0 * sc4.x;  sh4.y = bb.y - m1 * sc4.y;
        sh4.z = bb.z - m2 * sc4.z;  sh4.w = bb.w - m3 * sc4.w;
    }
    float4 wd4 = *(const float4*)(Wd + 4 * lane16);
    float bdv = bd[0];

    float acc = 0.f;
    for (int base = gw * 8; base < 2 * EE; base += nw * 8) {
        // EE % 8 == 0 and base % 8 == 0 => chunk is purely pos or purely neg
        float y; const int* src; int off0;
        if (base < EE) { src = target; off0 = base;      y = 1.f; }
        else           { src = negp;   off0 = base - EE; y = 0.f; }
#pragma unroll
        for (int j = 0; j < 4; j++) {
            int p = off0 + 2 * j + half;
            int u = src[p], v = src[EE + p];
            float4 zu = *(const float4*)(g_z2 + u * OUT + 4 * lane16);
            float4 zv = *(const float4*)(g_z2 + v * OUT + 4 * lane16);
            float eu0 = fmaxf(fmaf(zu.x, sc4.x, sh4.x), 0.f);
            float eu1 = fmaxf(fmaf(zu.y, sc4.y, sh4.y), 0.f);
            float eu2 = fmaxf(fmaf(zu.z, sc4.z, sh4.z), 0.f);
            float eu3 = fmaxf(fmaf(zu.w, sc4.w, sh4.w), 0.f);
            float ev0 = fmaxf(fmaf(zv.x, sc4.x, sh4.x), 0.f);
            float ev1 = fmaxf(fmaf(zv.y, sc4.y, sh4.y), 0.f);
            float ev2 = fmaxf(fmaf(zv.z, sc4.z, sh4.z), 0.f);
            float ev3 = fmaxf(fmaf(zv.w, sc4.w, sh4.w), 0.f);
            float d = eu0 * ev0 * wd4.x + eu1 * ev1 * wd4.y
                    + eu2 * ev2 * wd4.z + eu3 * ev3 * wd4.w;
#pragma unroll
            for (int s = 8; s > 0; s >>= 1) d += __shfl_xor_sync(FULL, d, s);
            if (lane16 == 0) {
                float pr = d + bdv;
                acc += fmaxf(pr, 0.f) - pr * y + log1pf(__expf(-fabsf(pr)));
            }
        }
    }
    acc += __shfl_xor_sync(FULL, acc, 16);
    __shared__ float ws[8];
    if (lane == 0) ws[w] = acc;
    __syncthreads();

    // cleanup for next replay: g_cnt / g_s1 are not read by this kernel
    {
        int gid = blockIdx.x * blockDim.x + t;
        int stride = gridDim.x * blockDim.x;
        for (int i = gid; i < MTOT; i += stride) g_cnt[i] = 0;
        if (gid < 2 * HID) g_s1[gid] = 0.f;
    }

    if (t == 0) {
        float s = 0.f;
#pragma unroll
        for (int i = 0; i < 8; i++) s += ws[i];
        atomicAdd(&g_loss, (double)s);
        __threadfence();
        unsigned ticket = atomicAdd(&g_done, 1u);
        if (ticket == gridDim.x - 1) {
            out[0] = (float)(g_loss * (1.0 / (double)(2 * EE)));
            // winner runs strictly after all blocks read their BN2 params
            for (int i = 0; i < 2 * OUT; i++) g_s2[i] = 0.f;
            g_loss = 0.0;
            g_done = 0u;
        }
    }
}

// ---------------- launch ------------------------------------------------------
extern "C" void kernel_launch(void* const* d_in, const int* in_sizes, int n_in,
                              void* d_out, int out_size) {
    const float* x        = (const float*)d_in[0];
    const float* node_ts  = (const float*)d_in[1];
    const int*   nidx     = (const int*)  d_in[2];
    const float* nts      = (const float*)d_in[3];
    const int*   target   = (const int*)  d_in[4];
    const int*   negp     = (const int*)  d_in[5];
    const float* W1       = (const float*)d_in[6];
    const float* g1       = (const float*)d_in[8];
    const float* be1      = (const float*)d_in[9];
    const float* W2       = (const float*)d_in[10];
    const float* g2       = (const float*)d_in[12];
    const float* be2      = (const float*)d_in[13];
    const float* Wd       = (const float*)d_in[14];
    const float* bd       = (const float*)d_in[15];
    float* out = (float*)d_out;

    k_xw1   <<<1024, 128>>>(x, W1, node_ts, nidx, nts);
    k_build <<<2500, 256>>>(nidx, nts);
    k_agg   <<<2500, 256>>>(g1, be1);
    k_gemm2 <<<1250, 256>>>(W2);
    k_dec   <<<1600, 256>>>(target, negp, Wd, bd, g2, be2, out);
}